// round 3
// baseline (speedup 1.0000x reference)
#include <cuda_runtime.h>
#include <cuda_bf16.h>

// RankingLoss: out = mean(1/(pred^2+eps)) + [ sum_{i:neg, j:pos} relu(pred_j - pred_i) ] / (n_neg*n_pos)
// DELTA = 0, EPS = 1e-5, B = 8192.
// NOTE: target is int32 on the wire (JAX without x64 silently downcasts int64 -> int32).

#define J_TILE   1024
#define BLOCK    256
#define MAX_PART 8192

__device__ double g_partials[MAX_PART];

__global__ __launch_bounds__(BLOCK)
void rank_pair_kernel(const float* __restrict__ pred,
                      const int* __restrict__ target,
                      int B) {
    __shared__ float sj[J_TILE];
    const int tid = threadIdx.x;
    const int j0 = blockIdx.y * J_TILE;

    // Stage j-tile: positive-labeled preds, others -> -1e30 (relu kills them)
    #pragma unroll
    for (int j = tid; j < J_TILE; j += BLOCK) {
        const int jj = j0 + j;
        float v = -1e30f;
        if (jj < B && target[jj] == 1) v = pred[jj];
        sj[j] = v;
    }
    __syncthreads();

    const int i = blockIdx.x * BLOCK + tid;
    float pi = 0.0f;
    bool active = false;
    if (i < B) {
        pi = pred[i];
        active = (target[i] == 0);
    }

    // Vectorized inner loop over the j-tile (broadcast LDS.128, 4 accumulators)
    const float4* sj4 = reinterpret_cast<const float4*>(sj);
    float a0 = 0.f, a1 = 0.f, a2 = 0.f, a3 = 0.f;
    #pragma unroll 8
    for (int j = 0; j < J_TILE / 4; ++j) {
        const float4 v = sj4[j];
        a0 += fmaxf(v.x - pi, 0.0f);
        a1 += fmaxf(v.y - pi, 0.0f);
        a2 += fmaxf(v.z - pi, 0.0f);
        a3 += fmaxf(v.w - pi, 0.0f);
    }
    float acc = (a0 + a1) + (a2 + a3);
    if (!active) acc = 0.0f;

    // Warp reduce (double), then cross-warp via smem
    double d = (double)acc;
    #pragma unroll
    for (int off = 16; off > 0; off >>= 1)
        d += __shfl_down_sync(0xFFFFFFFFu, d, off);

    __shared__ double wsum[BLOCK / 32];
    const int wid = tid >> 5;
    const int lid = tid & 31;
    if (lid == 0) wsum[wid] = d;
    __syncthreads();
    if (wid == 0) {
        double t = (lid < BLOCK / 32) ? wsum[lid] : 0.0;
        #pragma unroll
        for (int off = 4; off > 0; off >>= 1)
            t += __shfl_down_sync(0xFFFFFFFFu, t, off);
        if (lid == 0)
            g_partials[blockIdx.y * gridDim.x + blockIdx.x] = t;
    }
}

__global__ __launch_bounds__(BLOCK)
void rank_finalize_kernel(const float* __restrict__ pred,
                          const int* __restrict__ target,
                          float* __restrict__ out,
                          int B, int nPartials) {
    const int tid = threadIdx.x;

    double loss = 0.0;
    for (int p = tid; p < nPartials; p += BLOCK) loss += g_partials[p];

    double triv = 0.0;
    int neg = 0;
    for (int idx = tid; idx < B; idx += BLOCK) {
        const float p = pred[idx];
        triv += 1.0 / ((double)p * (double)p + 1e-5);
        neg += (target[idx] == 0) ? 1 : 0;
    }

    __shared__ double s_loss[BLOCK];
    __shared__ double s_triv[BLOCK];
    __shared__ int    s_neg[BLOCK];
    s_loss[tid] = loss;
    s_triv[tid] = triv;
    s_neg[tid]  = neg;
    __syncthreads();
    #pragma unroll
    for (int s = BLOCK / 2; s > 0; s >>= 1) {
        if (tid < s) {
            s_loss[tid] += s_loss[tid + s];
            s_triv[tid] += s_triv[tid + s];
            s_neg[tid]  += s_neg[tid + s];
        }
        __syncthreads();
    }

    if (tid == 0) {
        const double n_neg = (double)s_neg[0];
        const double n_pos = (double)B - n_neg;
        const double N = n_neg * n_pos;
        const double result = s_triv[0] / (double)B + s_loss[0] / N;
        out[0] = (float)result;
    }
}

extern "C" void kernel_launch(void* const* d_in, const int* in_sizes, int n_in,
                              void* d_out, int out_size) {
    const float* pred   = (const float*)d_in[0];
    const int*   target = (const int*)d_in[1];
    float*       out    = (float*)d_out;
    const int B = in_sizes[0];

    const int gx = (B + BLOCK - 1) / BLOCK;
    const int gy = (B + J_TILE - 1) / J_TILE;
    dim3 grid(gx, gy);

    rank_pair_kernel<<<grid, BLOCK>>>(pred, target, B);
    rank_finalize_kernel<<<1, BLOCK>>>(pred, target, out, B, gx * gy);
}

// round 4
// speedup vs baseline: 1.7790x; 1.7790x over previous
#include <cuda_runtime.h>
#include <cuda_bf16.h>

// RankingLoss: out = mean(1/(pred^2+eps)) + [ sum_{i:neg, j:pos} relu(pred_j - pred_i) ] / (n_neg*n_pos)
// DELTA = 0, EPS = 1e-5, B = 8192. target is int32 on the wire.
//
// Single fused kernel, grid (B/BLOCK, B/J_TILE) = (32, 8):
//  - every block: pairwise hinge partial for its (i-slab, j-tile)
//  - blocks with by==0: also per-element trivial term (f32, like the reference) + neg count
//  - last block to finish (fence + self-resetting ticket) reduces all partials and writes out.

#define J_TILE   1024
#define BLOCK    256
#define GX       32     // 8192 / BLOCK
#define GY       8      // 8192 / J_TILE
#define NPART    (GX * GY)

__device__ double       g_pair[NPART];
__device__ double       g_triv[GX];
__device__ int          g_neg[GX];
__device__ unsigned int g_ticket;   // zero-init; atomicInc wraps -> self-resets each replay

__global__ __launch_bounds__(BLOCK)
void rank_fused_kernel(const float* __restrict__ pred,
                       const int* __restrict__ target,
                       float* __restrict__ out,
                       int B) {
    __shared__ float sj[J_TILE];
    const int tid = threadIdx.x;
    const int bx  = blockIdx.x;
    const int by  = blockIdx.y;
    const int j0  = by * J_TILE;

    // Stage j-tile: positive-labeled preds, others -> -1e30 (relu kills them)
    #pragma unroll
    for (int j = tid; j < J_TILE; j += BLOCK) {
        const int jj = j0 + j;
        float v = -1e30f;
        if (jj < B && target[jj] == 1) v = pred[jj];
        sj[j] = v;
    }
    __syncthreads();

    const int i = bx * BLOCK + tid;
    float pi = 0.0f;
    int   tg = 1;
    if (i < B) { pi = pred[i]; tg = target[i]; }
    const bool is_neg = (i < B) && (tg == 0);

    // Inner loop: broadcast LDS.128, 4 accumulators
    const float4* sj4 = reinterpret_cast<const float4*>(sj);
    float a0 = 0.f, a1 = 0.f, a2 = 0.f, a3 = 0.f;
    #pragma unroll 8
    for (int j = 0; j < J_TILE / 4; ++j) {
        const float4 v = sj4[j];
        a0 += fmaxf(v.x - pi, 0.0f);
        a1 += fmaxf(v.y - pi, 0.0f);
        a2 += fmaxf(v.z - pi, 0.0f);
        a3 += fmaxf(v.w - pi, 0.0f);
    }
    float acc = (a0 + a1) + (a2 + a3);
    if (!is_neg) acc = 0.0f;

    // Warp reduce pair partial (double), then cross-warp via smem
    double d = (double)acc;
    #pragma unroll
    for (int off = 16; off > 0; off >>= 1)
        d += __shfl_down_sync(0xFFFFFFFFu, d, off);

    __shared__ double wsum[BLOCK / 32];
    const int wid = tid >> 5;
    const int lid = tid & 31;
    if (lid == 0) wsum[wid] = d;
    __syncthreads();
    if (wid == 0) {
        double t = (lid < BLOCK / 32) ? wsum[lid] : 0.0;
        #pragma unroll
        for (int off = 4; off > 0; off >>= 1)
            t += __shfl_down_sync(0xFFFFFFFFu, t, off);
        if (lid == 0) g_pair[by * GX + bx] = t;
    }

    // by==0 blocks: trivial term (f32 per-element, matching reference) + neg count
    if (by == 0) {
        float tv = 0.0f;
        if (i < B) tv = 1.0f / (pi * pi + 1e-5f);
        double td = (double)tv;
        int    nc = is_neg ? 1 : 0;
        #pragma unroll
        for (int off = 16; off > 0; off >>= 1) {
            td += __shfl_down_sync(0xFFFFFFFFu, td, off);
            nc += __shfl_down_sync(0xFFFFFFFFu, nc, off);
        }
        __shared__ double twsum[BLOCK / 32];
        __shared__ int    nwsum[BLOCK / 32];
        if (lid == 0) { twsum[wid] = td; nwsum[wid] = nc; }
        __syncthreads();
        if (wid == 0) {
            double tt = (lid < BLOCK / 32) ? twsum[lid] : 0.0;
            int    nn = (lid < BLOCK / 32) ? nwsum[lid] : 0;
            #pragma unroll
            for (int off = 4; off > 0; off >>= 1) {
                tt += __shfl_down_sync(0xFFFFFFFFu, tt, off);
                nn += __shfl_down_sync(0xFFFFFFFFu, nn, off);
            }
            if (lid == 0) { g_triv[bx] = tt; g_neg[bx] = nn; }
        }
    }

    // Last-block-done final reduction (deterministic; ticket self-resets via wrap)
    __shared__ bool s_last;
    __threadfence();
    __syncthreads();
    if (tid == 0) {
        const unsigned int total = GX * GY;
        const unsigned int old = atomicInc(&g_ticket, total - 1u);
        s_last = (old == total - 1u);
    }
    __syncthreads();
    if (!s_last) return;

    // Reduce NPART pair partials + GX trivial partials + GX neg counts
    double lp = 0.0, lt = 0.0;
    int    ln = 0;
    for (int p = tid; p < NPART; p += BLOCK) lp += g_pair[p];
    if (tid < GX) { lt = g_triv[tid]; ln = g_neg[tid]; }

    #pragma unroll
    for (int off = 16; off > 0; off >>= 1) {
        lp += __shfl_down_sync(0xFFFFFFFFu, lp, off);
        lt += __shfl_down_sync(0xFFFFFFFFu, lt, off);
        ln += __shfl_down_sync(0xFFFFFFFFu, ln, off);
    }
    __shared__ double fp[BLOCK / 32];
    __shared__ double ft[BLOCK / 32];
    __shared__ int    fn[BLOCK / 32];
    if (lid == 0) { fp[wid] = lp; ft[wid] = lt; fn[wid] = ln; }
    __syncthreads();
    if (tid == 0) {
        double sp = 0.0, st = 0.0;
        int    sn = 0;
        #pragma unroll
        for (int w = 0; w < BLOCK / 32; ++w) { sp += fp[w]; st += ft[w]; sn += fn[w]; }
        const double n_neg = (double)sn;
        const double n_pos = (double)B - n_neg;
        const double N = n_neg * n_pos;
        out[0] = (float)(st / (double)B + sp / N);
    }
}

extern "C" void kernel_launch(void* const* d_in, const int* in_sizes, int n_in,
                              void* d_out, int out_size) {
    const float* pred   = (const float*)d_in[0];
    const int*   target = (const int*)d_in[1];
    float*       out    = (float*)d_out;
    const int B = in_sizes[0];

    dim3 grid(GX, GY);
    rank_fused_kernel<<<grid, BLOCK>>>(pred, target, out, B);
}